// round 3
// baseline (speedup 1.0000x reference)
#include <cuda_runtime.h>

// Problem shape fixed by setup_inputs(): x = (2, 4, 8, 256, 256) float32.
#define DD   8
#define HH   256
#define WW   256
#define NBC  8
#define HWsz 65536
#define DHWs 524288                  // 2^19
#define HT   4                       // h-rows per block tile
#define NTIL (HH / HT)               // 64
#define MAIN_BLOCKS (NBC * 6 * NTIL) // 3072 (interior d = 1..6)
#define COPY_BLOCKS (NBC * 2 * NTIL) // 1024 (d = 0, 7: pure defaults)

#define MAX_SHIFT 0.6f
#define BONUS     10.0f

// Worst case masked voxels = interior count = 8*6*254*254 = 3,096,768
__device__ int g_count;
__device__ int g_list[3100000];

// ---------------------------------------------------------------------------
// pass0: zero the append counter
__global__ void zero_kernel() { if (threadIdx.x == 0) g_count = 0; }

// ---------------------------------------------------------------------------
// One Newton step. Returns 0 = moved, 1 = converged (valid), 2 = invalid.
__device__ __forceinline__ int quad_step(
    float c000, float pxm, float pxp, float pym, float pyp, float psm, float psp,
    float e011, float e01m, float e0m1, float e0mm,
    float e101, float e10m, float em01, float em0m,
    float e110, float e1m0, float em10, float emm0,
    int& dc, int& hc, int& wc,
    float& shx, float& shy, float& shs, float& gds)
{
    float gx = 0.5f * (pxp - pxm);
    float gy = 0.5f * (pyp - pym);
    float gs = 0.5f * (psp - psm);
    float dxx = pxp - 2.0f * c000 + pxm;
    float dyy = pyp - 2.0f * c000 + pym;
    float dss = psp - 2.0f * c000 + psm;
    float dxy = 0.25f * (e011 - e01m - e0m1 + e0mm);
    float dxs = 0.25f * (e101 - e10m - em01 + em0m);
    float dys = 0.25f * (e110 - e1m0 - em10 + emm0);

    float cf00 = dyy * dss - dys * dys;
    float cf01 = dxy * dss - dys * dxs;
    float cf02 = dxy * dys - dyy * dxs;
    float det  = dxx * cf00 - dxy * cf01 + dxs * cf02;
    if (!(fabsf(det) > 0.0f)) return 2;

    float r0 = -gx, r1 = -gy, r2 = -gs;
    float sx = (r0 * cf00 - dxy * (r1 * dss - dys * r2) + dxs * (r1 * dys - dyy * r2)) / det;
    float sy = (dxx * (r1 * dss - dys * r2) - r0 * cf01 + dxs * (dxy * r2 - r1 * dxs)) / det;
    float ss = (dxx * (dyy * r2 - r1 * dys) - dxy * (dxy * r2 - r1 * dxs) + r0 * cf02) / det;

    shx = sx; shy = sy; shs = ss;
    gds = gx * sx + gy * sy + gs * ss;

    int mvx = (sx > MAX_SHIFT) ? 1 : ((sx < -MAX_SHIFT) ? -1 : 0);
    int nw = wc + mvx;
    if (nw < 1 || nw > WW - 2) return 2;
    wc = nw;
    int mvy = (sy > MAX_SHIFT) ? 1 : ((sy < -MAX_SHIFT) ? -1 : 0);
    int nh = hc + mvy;
    if (nh < 1 || nh > HH - 2) return 2;
    hc = nh;
    int mvs = (ss > MAX_SHIFT) ? 1 : ((ss < -MAX_SHIFT) ? -1 : 0);
    int nd = dc + mvs;
    if (nd < 1 || nd > DD - 2) return 2;
    dc = nd;

    return ((mvx | mvy | mvs) == 0) ? 1 : 0;
}

// ---------------------------------------------------------------------------
// pass1: NMS mask + default outputs + append masked voxel ids
__global__ __launch_bounds__(128)
void mask_kernel(const float* __restrict__ x, float* __restrict__ out)
{
    const int tid = threadIdx.x;
    const int blk = blockIdx.x;
    const int lane = tid & 31;

    if (blk < MAIN_BLOCKS) {
        const int t  = blk & (NTIL - 1);
        const int q  = blk / NTIL;
        const int d  = (q % 6) + 1;          // 1..6
        const int bc = q / 6;
        const int h0 = t * HT;

        const float* __restrict__ xb  = x + (size_t)bc * DHWs;
        const float2* __restrict__ xb2 = (const float2*)xb;
        const int w2 = tid << 1;

        __shared__ float sfull[2][WW];

        const int baseidx = d * (HWsz / 2) + tid;

        float2 A0, A1, A2, B0, B1, B2, C0, C1, C2;
        {
            int hm = h0 - 1; if (hm < 0) hm = 0;
            A0 = xb2[baseidx - (HWsz / 2) + hm * (WW / 2)];
            A1 = xb2[baseidx               + hm * (WW / 2)];
            A2 = xb2[baseidx + (HWsz / 2) + hm * (WW / 2)];
            B0 = xb2[baseidx - (HWsz / 2) + h0 * (WW / 2)];
            B1 = xb2[baseidx               + h0 * (WW / 2)];
            B2 = xb2[baseidx + (HWsz / 2) + h0 * (WW / 2)];
        }

        float* __restrict__ ob = out + (size_t)bc * 3 * DHWs + d * HWsz + h0 * WW;
        float* __restrict__ oy = out + (size_t)NBC * 3 * DHWs + (size_t)bc * DHWs
                                     + d * HWsz + h0 * WW;

        const float fw0 = (float)w2, fw1 = (float)(w2 + 1);
        const float fdd = (float)d;
        const int sp_row0 = d * HWsz + h0 * WW + w2;
        const int idx_base = bc * DHWs + sp_row0;

#pragma unroll
        for (int r = 0; r < HT; ++r) {
            const int h = h0 + r;
            int hc1 = h + 1; if (hc1 > HH - 1) hc1 = HH - 1;
            C0 = xb2[baseidx - (HWsz / 2) + hc1 * (WW / 2)];
            C1 = xb2[baseidx               + hc1 * (WW / 2)];
            C2 = xb2[baseidx + (HWsz / 2) + hc1 * (WW / 2)];

            float ex0 = fmaxf(A0.x, A1.x); ex0 = fmaxf(ex0, A2.x);
            ex0 = fmaxf(ex0, B0.x); ex0 = fmaxf(ex0, B2.x);
            ex0 = fmaxf(ex0, C0.x); ex0 = fmaxf(ex0, C1.x); ex0 = fmaxf(ex0, C2.x);
            float ex1 = fmaxf(A0.y, A1.y); ex1 = fmaxf(ex1, A2.y);
            ex1 = fmaxf(ex1, B0.y); ex1 = fmaxf(ex1, B2.y);
            ex1 = fmaxf(ex1, C0.y); ex1 = fmaxf(ex1, C1.y); ex1 = fmaxf(ex1, C2.y);

            const float c0 = B1.x, c1 = B1.y;
            const float full0 = fmaxf(ex0, c0), full1 = fmaxf(ex1, c1);
            const int par = r & 1;
            *(float2*)&sfull[par][w2] = make_float2(full0, full1);
            __syncthreads();
            int il = w2 - 1; if (il < 0) il = 0;
            int ir = w2 + 2; if (ir > WW - 1) ir = WW - 1;
            const float fl = sfull[par][il];
            const float fr = sfull[par][ir];

            const bool hin = (h >= 1) & (h <= HH - 2);
            const bool m0 = hin & (w2 >= 1)      & (c0 > fmaxf(ex0, fmaxf(fl, full1)));
            const bool m1 = hin & (w2 <= WW - 3) & (c1 > fmaxf(ex1, fmaxf(full0, fr)));

            // warp-aggregated append of masked voxel ids
            unsigned b0 = __ballot_sync(0xffffffffu, m0);
            unsigned b1 = __ballot_sync(0xffffffffu, m1);
            if (b0 | b1) {
                int n = __popc(b0) + __popc(b1);
                int leader = __ffs(b0 | b1) - 1;
                int base;
                if (lane == leader) base = atomicAdd(&g_count, n);
                base = __shfl_sync(0xffffffffu, base, leader);
                unsigned lt = (lane == 31) ? 0xffffffffu >> 1 : ((1u << lane) - 1u);
                const int vidx = idx_base + r * WW;
                if (m0) g_list[base + __popc(b0 & lt)] = vidx;
                if (m1) g_list[base + __popc(b0) + __popc(b1 & lt)] = vidx + 1;
            }

            // default outputs everywhere; pass2 overwrites valid maxima
            const float fhh = (float)h;
            const int ro = r * WW + w2;
            *(float2*)&ob[0 * DHWs + ro] = make_float2(fdd, fdd);
            *(float2*)&ob[1 * DHWs + ro] = make_float2(fw0, fw1);
            *(float2*)&ob[2 * DHWs + ro] = make_float2(fhh, fhh);
            *(float2*)&oy[ro]            = make_float2(c0, c1);

            A0 = B0; A1 = B1; A2 = B2;
            B0 = C0; B1 = C1; B2 = C2;
        }
    } else {
        // copy path: d = 0 and d = 7 are pure defaults
        const int blk2 = blk - MAIN_BLOCKS;
        const int t  = blk2 & (NTIL - 1);
        const int q  = blk2 / NTIL;
        const int d  = (q & 1) ? (DD - 1) : 0;
        const int bc = q >> 1;
        const int h0 = t * HT;

        const float4* __restrict__ xb4 =
            (const float4*)(x + (size_t)bc * DHWs + d * HWsz + h0 * WW);
        float* __restrict__ ob = out + (size_t)bc * 3 * DHWs + d * HWsz + h0 * WW;
        float* __restrict__ oy = out + (size_t)NBC * 3 * DHWs + (size_t)bc * DHWs
                                     + d * HWsz + h0 * WW;
        const float fdd = (float)d;

#pragma unroll
        for (int i = 0; i < (HT * WW / 4) / 128; ++i) {
            const int idx = i * 128 + tid;
            const int row = idx >> 6;
            const int wq  = (idx & 63) << 2;
            const float4 c = xb4[idx];
            const float fh = (float)(h0 + row);
            const int off = row * WW + wq;
            *(float4*)&ob[0 * DHWs + off] = make_float4(fdd, fdd, fdd, fdd);
            *(float4*)&ob[1 * DHWs + off] =
                make_float4((float)wq, (float)(wq + 1), (float)(wq + 2), (float)(wq + 3));
            *(float4*)&ob[2 * DHWs + off] = make_float4(fh, fh, fh, fh);
            *(float4*)&oy[off] = c;
        }
    }
}

// ---------------------------------------------------------------------------
// pass2: 5-iteration Newton refinement over the compacted masked-voxel list
__global__ __launch_bounds__(128)
void refine_kernel(const float* __restrict__ x, float* __restrict__ out)
{
    const int total = g_count;
    const int stride = gridDim.x * blockDim.x;
#pragma unroll 1
    for (int i = blockIdx.x * blockDim.x + threadIdx.x; i < total; i += stride) {
        const int idx = g_list[i];
        const int bc  = idx >> 19;
        const int sp  = idx & (DHWs - 1);
        const int d   = sp >> 16;
        const int h   = (sp >> 8) & 255;
        const int w   = sp & 255;
        const float* __restrict__ xb = x + (size_t)bc * DHWs;

        int dc = d, hc = h, wc = w;
        float shx = 0.f, shy = 0.f, shs = 0.f, gds = 0.f;
        int st = 0;

#pragma unroll 1
        for (int it = 0; (it < 5) && (st == 0); ++it) {
            int ds_ = min(max(dc, 1), DD - 2);
            int hs_ = min(max(hc, 1), HH - 2);
            int ws_ = min(max(wc, 1), WW - 2);
            const float* p = xb + ds_ * HWsz + hs_ * WW + ws_;
            st = quad_step(p[0],
                p[-1], p[1], p[-WW], p[WW], p[-HWsz], p[HWsz],
                p[WW + 1], p[WW - 1], p[-WW + 1], p[-WW - 1],
                p[HWsz + 1], p[HWsz - 1], p[-HWsz + 1], p[-HWsz - 1],
                p[HWsz + WW], p[HWsz - WW], p[-HWsz + WW], p[-HWsz - WW],
                dc, hc, wc, shx, shy, shs, gds);
        }

        bool valid = (st != 2)
                   && (fabsf(shx) <= 1.5f) && (fabsf(shy) <= 1.5f) && (fabsf(shs) <= 1.5f);
        if (valid) {
            const int cb = bc * 3 * DHWs;
            out[cb + 0 * DHWs + sp] = (float)dc + shs;
            out[cb + 1 * DHWs + sp] = (float)wc + shx;
            out[cb + 2 * DHWs + sp] = (float)hc + shy;
            out[(size_t)NBC * 3 * DHWs + (size_t)bc * DHWs + sp] =
                xb[sp] + (0.5f * gds + BONUS);
        }
    }
}

extern "C" void kernel_launch(void* const* d_in, const int* in_sizes, int n_in,
                              void* d_out, int out_size)
{
    (void)in_sizes; (void)n_in; (void)out_size;
    const float* x = (const float*)d_in[0];
    float* out = (float*)d_out;
    zero_kernel<<<1, 32>>>();
    mask_kernel<<<MAIN_BLOCKS + COPY_BLOCKS, 128>>>(x, out);
    refine_kernel<<<2048, 128>>>(x, out);
}

// round 4
// speedup vs baseline: 2.1474x; 2.1474x over previous
#include <cuda_runtime.h>

// Problem shape fixed by setup_inputs(): x = (2, 4, 8, 256, 256) float32.
#define DD   8
#define HH   256
#define WW   256
#define NBC  8
#define HWsz 65536
#define DHWs 524288                  // 2^19
#define HT   8                       // h-rows per block tile
#define NTIL (HH / HT)               // 32
#define MAIN_BLOCKS (NBC * 6 * NTIL) // 1536 (interior d = 1..6)
#define COPY_BLOCKS (NBC * 2 * NTIL) // 512  (d = 0, 7: pure defaults)

#define MAX_SHIFT 0.6f
#define BONUS     10.0f

// One Newton step. Returns 0 = moved, 1 = converged (valid), 2 = invalid.
__device__ __forceinline__ int quad_step(
    float c000, float pxm, float pxp, float pym, float pyp, float psm, float psp,
    float e011, float e01m, float e0m1, float e0mm,
    float e101, float e10m, float em01, float em0m,
    float e110, float e1m0, float em10, float emm0,
    int& dc, int& hc, int& wc,
    float& shx, float& shy, float& shs, float& gds)
{
    float gx = 0.5f * (pxp - pxm);
    float gy = 0.5f * (pyp - pym);
    float gs = 0.5f * (psp - psm);
    float dxx = pxp - 2.0f * c000 + pxm;
    float dyy = pyp - 2.0f * c000 + pym;
    float dss = psp - 2.0f * c000 + psm;
    float dxy = 0.25f * (e011 - e01m - e0m1 + e0mm);
    float dxs = 0.25f * (e101 - e10m - em01 + em0m);
    float dys = 0.25f * (e110 - e1m0 - em10 + emm0);

    float cf00 = dyy * dss - dys * dys;
    float cf01 = dxy * dss - dys * dxs;
    float cf02 = dxy * dys - dyy * dxs;
    float det  = dxx * cf00 - dxy * cf01 + dxs * cf02;
    if (!(fabsf(det) > 0.0f)) return 2;

    float r0 = -gx, r1 = -gy, r2 = -gs;
    float sx = (r0 * cf00 - dxy * (r1 * dss - dys * r2) + dxs * (r1 * dys - dyy * r2)) / det;
    float sy = (dxx * (r1 * dss - dys * r2) - r0 * cf01 + dxs * (dxy * r2 - r1 * dxs)) / det;
    float ss = (dxx * (dyy * r2 - r1 * dys) - dxy * (dxy * r2 - r1 * dxs) + r0 * cf02) / det;

    shx = sx; shy = sy; shs = ss;
    gds = gx * sx + gy * sy + gs * ss;

    int mvx = (sx > MAX_SHIFT) ? 1 : ((sx < -MAX_SHIFT) ? -1 : 0);
    int nw = wc + mvx;
    if (nw < 1 || nw > WW - 2) return 2;
    wc = nw;
    int mvy = (sy > MAX_SHIFT) ? 1 : ((sy < -MAX_SHIFT) ? -1 : 0);
    int nh = hc + mvy;
    if (nh < 1 || nh > HH - 2) return 2;
    hc = nh;
    int mvs = (ss > MAX_SHIFT) ? 1 : ((ss < -MAX_SHIFT) ? -1 : 0);
    int nd = dc + mvs;
    if (nd < 1 || nd > DD - 2) return 2;
    dc = nd;

    return ((mvx | mvy | mvs) == 0) ? 1 : 0;
}

__global__ __launch_bounds__(128)
void iqi3d_kernel(const float* __restrict__ x, float* __restrict__ out)
{
    const int tid = threadIdx.x;
    const int blk = blockIdx.x;
    const int lane = tid & 31;

    if (blk < MAIN_BLOCKS) {
        // =========== phase 1: mask + defaults + shared-list append ===========
        const int t  = blk & (NTIL - 1);
        const int q  = blk / NTIL;
        const int d  = (q % 6) + 1;          // 1..6
        const int bc = q / 6;
        const int h0 = t * HT;

        const float* __restrict__ xb  = x + (size_t)bc * DHWs;
        const float2* __restrict__ xb2 = (const float2*)xb;
        const int w2 = tid << 1;

        __shared__ float sfull[2][WW];
        __shared__ unsigned short slist[512];   // strict maxima pack bound: 4*128
        __shared__ int scount;

        if (tid == 0) scount = 0;

        const int baseidx = d * (HWsz / 2) + tid;

        float2 A0, A1, A2, B0, B1, B2, C0, C1, C2;
        {
            int hm = h0 - 1; if (hm < 0) hm = 0;
            A0 = xb2[baseidx - (HWsz / 2) + hm * (WW / 2)];
            A1 = xb2[baseidx               + hm * (WW / 2)];
            A2 = xb2[baseidx + (HWsz / 2) + hm * (WW / 2)];
            B0 = xb2[baseidx - (HWsz / 2) + h0 * (WW / 2)];
            B1 = xb2[baseidx               + h0 * (WW / 2)];
            B2 = xb2[baseidx + (HWsz / 2) + h0 * (WW / 2)];
        }

        float* __restrict__ ob = out + (size_t)bc * 3 * DHWs + d * HWsz + h0 * WW;
        float* __restrict__ oy = out + (size_t)NBC * 3 * DHWs + (size_t)bc * DHWs
                                     + d * HWsz + h0 * WW;

        const float fw0 = (float)w2, fw1 = (float)(w2 + 1);
        const float fdd = (float)d;

#pragma unroll
        for (int r = 0; r < HT; ++r) {
            const int h = h0 + r;
            int hc1 = h + 1; if (hc1 > HH - 1) hc1 = HH - 1;
            C0 = xb2[baseidx - (HWsz / 2) + hc1 * (WW / 2)];
            C1 = xb2[baseidx               + hc1 * (WW / 2)];
            C2 = xb2[baseidx + (HWsz / 2) + hc1 * (WW / 2)];

            float ex0 = fmaxf(A0.x, A1.x); ex0 = fmaxf(ex0, A2.x);
            ex0 = fmaxf(ex0, B0.x); ex0 = fmaxf(ex0, B2.x);
            ex0 = fmaxf(ex0, C0.x); ex0 = fmaxf(ex0, C1.x); ex0 = fmaxf(ex0, C2.x);
            float ex1 = fmaxf(A0.y, A1.y); ex1 = fmaxf(ex1, A2.y);
            ex1 = fmaxf(ex1, B0.y); ex1 = fmaxf(ex1, B2.y);
            ex1 = fmaxf(ex1, C0.y); ex1 = fmaxf(ex1, C1.y); ex1 = fmaxf(ex1, C2.y);

            const float c0 = B1.x, c1 = B1.y;
            const float full0 = fmaxf(ex0, c0), full1 = fmaxf(ex1, c1);
            const int par = r & 1;
            *(float2*)&sfull[par][w2] = make_float2(full0, full1);
            __syncthreads();
            int il = w2 - 1; if (il < 0) il = 0;
            int ir = w2 + 2; if (ir > WW - 1) ir = WW - 1;
            const float fl = sfull[par][il];
            const float fr = sfull[par][ir];

            const bool hin = (h >= 1) & (h <= HH - 2);
            const bool m0 = hin & (w2 >= 1)      & (c0 > fmaxf(ex0, fmaxf(fl, full1)));
            const bool m1 = hin & (w2 <= WW - 3) & (c1 > fmaxf(ex1, fmaxf(full0, fr)));

            // warp-aggregated append to the block-local list
            unsigned b0 = __ballot_sync(0xffffffffu, m0);
            unsigned b1 = __ballot_sync(0xffffffffu, m1);
            if (b0 | b1) {
                int n = __popc(b0) + __popc(b1);
                int leader = __ffs(b0 | b1) - 1;
                int base;
                if (lane == leader) base = atomicAdd(&scount, n);
                base = __shfl_sync(0xffffffffu, base, leader);
                unsigned lt = (lane == 31) ? 0x7fffffffu : ((1u << lane) - 1u);
                const int code = (r << 8) | w2;
                if (m0) slist[base + __popc(b0 & lt)] = (unsigned short)code;
                if (m1) slist[base + __popc(b0) + __popc(b1 & lt)] = (unsigned short)(code + 1);
            }

            // default outputs everywhere; phase 2 overwrites valid maxima
            const float fhh = (float)h;
            const int ro = r * WW + w2;
            *(float2*)&ob[0 * DHWs + ro] = make_float2(fdd, fdd);
            *(float2*)&ob[1 * DHWs + ro] = make_float2(fw0, fw1);
            *(float2*)&ob[2 * DHWs + ro] = make_float2(fhh, fhh);
            *(float2*)&oy[ro]            = make_float2(c0, c1);

            A0 = B0; A1 = B1; A2 = B2;
            B0 = C0; B1 = C1; B2 = C2;
        }

        // =========== phase 2: cooperative refine over compacted list ===========
        __syncthreads();
        const int cnt = scount;
#pragma unroll 1
        for (int i = tid; i < cnt; i += 128) {
            const int code = slist[i];
            const int r = code >> 8;
            const int w = code & 255;
            const int h = h0 + r;
            const int sp = d * HWsz + h * WW + w;

            int dc = d, hc = h, wc = w;
            float shx = 0.f, shy = 0.f, shs = 0.f, gds = 0.f;
            int st = 0;

#pragma unroll 1
            for (int it = 0; (it < 5) && (st == 0); ++it) {
                int ds_ = min(max(dc, 1), DD - 2);
                int hs_ = min(max(hc, 1), HH - 2);
                int ws_ = min(max(wc, 1), WW - 2);
                const float* p = xb + ds_ * HWsz + hs_ * WW + ws_;
                st = quad_step(p[0],
                    p[-1], p[1], p[-WW], p[WW], p[-HWsz], p[HWsz],
                    p[WW + 1], p[WW - 1], p[-WW + 1], p[-WW - 1],
                    p[HWsz + 1], p[HWsz - 1], p[-HWsz + 1], p[-HWsz - 1],
                    p[HWsz + WW], p[HWsz - WW], p[-HWsz + WW], p[-HWsz - WW],
                    dc, hc, wc, shx, shy, shs, gds);
            }

            bool valid = (st != 2)
                       && (fabsf(shx) <= 1.5f) && (fabsf(shy) <= 1.5f) && (fabsf(shs) <= 1.5f);
            if (valid) {
                const int cb = bc * 3 * DHWs;
                out[cb + 0 * DHWs + sp] = (float)dc + shs;
                out[cb + 1 * DHWs + sp] = (float)wc + shx;
                out[cb + 2 * DHWs + sp] = (float)hc + shy;
                out[(size_t)NBC * 3 * DHWs + (size_t)bc * DHWs + sp] =
                    xb[sp] + (0.5f * gds + BONUS);
            }
        }
    } else {
        // ---------- copy path: d = 0 and d = 7 are pure defaults ----------
        const int blk2 = blk - MAIN_BLOCKS;
        const int t  = blk2 & (NTIL - 1);
        const int q  = blk2 / NTIL;
        const int d  = (q & 1) ? (DD - 1) : 0;
        const int bc = q >> 1;
        const int h0 = t * HT;

        const float4* __restrict__ xb4 =
            (const float4*)(x + (size_t)bc * DHWs + d * HWsz + h0 * WW);
        float* __restrict__ ob = out + (size_t)bc * 3 * DHWs + d * HWsz + h0 * WW;
        float* __restrict__ oy = out + (size_t)NBC * 3 * DHWs + (size_t)bc * DHWs
                                     + d * HWsz + h0 * WW;
        const float fdd = (float)d;

#pragma unroll
        for (int i = 0; i < (HT * WW / 4) / 128; ++i) {
            const int idx = i * 128 + tid;
            const int row = idx >> 6;
            const int wq  = (idx & 63) << 2;
            const float4 c = xb4[idx];
            const float fh = (float)(h0 + row);
            const int off = row * WW + wq;
            *(float4*)&ob[0 * DHWs + off] = make_float4(fdd, fdd, fdd, fdd);
            *(float4*)&ob[1 * DHWs + off] =
                make_float4((float)wq, (float)(wq + 1), (float)(wq + 2), (float)(wq + 3));
            *(float4*)&ob[2 * DHWs + off] = make_float4(fh, fh, fh, fh);
            *(float4*)&oy[off] = c;
        }
    }
}

extern "C" void kernel_launch(void* const* d_in, const int* in_sizes, int n_in,
                              void* d_out, int out_size)
{
    (void)in_sizes; (void)n_in; (void)out_size;
    const float* x = (const float*)d_in[0];
    float* out = (float*)d_out;
    iqi3d_kernel<<<MAIN_BLOCKS + COPY_BLOCKS, 128>>>(x, out);
}